// round 14
// baseline (speedup 1.0000x reference)
#include <cuda_runtime.h>

// Eq3NetMini: B=8, N=48, EMBED=32, IN_DIM=33, N_OPS=8, HID=32
// y[b,h,i,j,k] = sum_d A[h,d]*x_j,d*x_k,d + R[h,j] + C[h,k] + base[h]
// FFMA2 main loop. R11: occupancy 3 (was 2) — shrink per-thread tile to
// 1j x 4k x 8h (acc = 32 regs) so regs fit the 112 cap at 576 thr/SM.
// Kernel was latency-bound at 3 warps/SMSP (fma 36%, issue 41%); 4.5
// warps/SMSP hides the LDS->FMA chains. R8's 16h tile spilled (regression).

#define NB 8
#define NN 48
#define ND 33
#define NH 32
#define NTHREADS 192
#define NBLOCKS (NB * NN)

typedef unsigned long long u64;

__device__ __forceinline__ u64 pack2(float lo, float hi) {
    u64 r; asm("mov.b64 %0,{%1,%2};" : "=l"(r) : "f"(lo), "f"(hi)); return r;
}
__device__ __forceinline__ void unpack2(u64 v, float& lo, float& hi) {
    asm("mov.b64 {%0,%1},%2;" : "=f"(lo), "=f"(hi) : "l"(v));
}
__device__ __forceinline__ u64 fma2(u64 a, u64 b, u64 c) {
    u64 r; asm("fma.rn.f32x2 %0,%1,%2,%3;" : "=l"(r) : "l"(a), "l"(b), "l"(c)); return r;
}
__device__ __forceinline__ u64 mul2(u64 a, u64 b) {
    u64 r; asm("mul.rn.f32x2 %0,%1,%2;" : "=l"(r) : "l"(a), "l"(b)); return r;
}
__device__ __forceinline__ u64 add2(u64 a, u64 b) {
    u64 r; asm("add.rn.f32x2 %0,%1,%2;" : "=l"(r) : "l"(a), "l"(b)); return r;
}

__device__ float g_partial[NB * NN * NH];
__device__ unsigned int g_done = 0;         // self-resets via atomicInc wrap

__global__ __launch_bounds__(NTHREADS, 3) void eq3_main(
    const int*   __restrict__ xcat,
    const float* __restrict__ xfeat,
    const float* __restrict__ embed,
    const float* __restrict__ coefs,     // (33, 8, 32): [d*256 + s*32 + h]
    const float* __restrict__ eq_bias,
    const float* __restrict__ out_w,
    const float* __restrict__ out_b,
    float*       __restrict__ out)
{
    __shared__ __align__(16) float  x_smT[ND * NN];   // x[d][row]
    __shared__ float  s_sm[ND];
    __shared__ float  base_sm[NH];
    __shared__ __align__(16) float2 A2_sm[ND * NH];   // {a,a} dup for f32x2
    __shared__ __align__(16) float2 BD_sm[ND * NH];   // {B,D} interleaved
    __shared__ __align__(16) float  R_sm[NH * NN];    // [h*48+j] (base folded)
    __shared__ __align__(16) float  C_sm[NH * NN];    // [h*48+k]
    __shared__ float  part_sm[6][NH];
    __shared__ bool   is_last;

    const int t = threadIdx.x;
    const int b = blockIdx.y;
    const int i = blockIdx.x;

    // ---- load x transposed ----
    for (int e = t; e < NN * ND; e += NTHREADS) {
        int d   = e / NN;
        int row = e - d * NN;
        x_smT[e] = (d < 32) ? embed[xcat[b * NN + row] * 32 + d]
                            : xfeat[b * NN + row];
    }
    __syncthreads();

    // ---- column means ----
    if (t < ND) {
        const float* xr = x_smT + t * NN;
        float su = 0.f;
        #pragma unroll 8
        for (int r = 0; r < NN; r++) su += xr[r];
        s_sm[t] = su * (1.0f / 48.0f);
    }
    __syncthreads();

    // ---- per-block coefficient combos ----
    for (int e = t; e < ND * NH; e += NTHREADS) {
        int d = e >> 5;
        int h = e & 31;
        float xi = x_smT[d * NN + i];
        float s  = s_sm[d];
        const float* c = coefs + d * 256 + h;
        float a = c[0] * xi + c[32] * s;                        // op0+op1
        A2_sm[e] = make_float2(a, a);
        BD_sm[e] = make_float2((c[96] * xi + c[160] * s) * s,   // B -> R(j)
                               (c[64] * xi + c[128] * s) * s);  // D -> C(k)
    }
    if (t < NH) {
        float acc = eq_bias[t];
        for (int d = 0; d < ND; d++) {
            float xi = x_smT[d * NN + i];
            float s  = s_sm[d];
            const float* c = coefs + d * 256 + t;
            acc += (c[192] * xi + c[224] * s) * s * s;          // op6+op7
        }
        base_sm[t] = acc;
    }
    __syncthreads();

    // ---- R[h,j] (base folded) and C[h,k], vectorized {r,cc} ----
    for (int e = t; e < NH * NN; e += NTHREADS) {
        int h = e / NN;
        int j = e - h * NN;
        u64 rc = pack2(base_sm[h], 0.f);
        const u64* bd = (const u64*)(BD_sm + h);
        #pragma unroll 3
        for (int d = 0; d < ND; d++) {
            float xv = x_smT[d * NN + j];
            rc = fma2(bd[d * NH], pack2(xv, xv), rc);
        }
        float r, cc;
        unpack2(rc, r, cc);
        R_sm[e] = r;
        C_sm[e] = cc;
    }
    __syncthreads();

    // ---- main: per-thread (1 j) x (4 k) x (8 h), 3 tiles, 4 h-chunks ----
    const int lane = t & 31;
    const int warp = t >> 5;

    for (int hc = 0; hc < 4; hc++) {
        const int hc8 = hc * 8;
        float pool[8];
        #pragma unroll
        for (int hh = 0; hh < 8; hh++) pool[hh] = 0.f;

        for (int tile = 0; tile < 3; tile++) {
            int p  = t + NTHREADS * tile;       // 0..575
            int j  = p / 12;                    // 0..47
            int k0 = (p - j * 12) * 4;          // 0,4,...,44

            u64 acc[8][2];
            #pragma unroll
            for (int hh = 0; hh < 8; hh++) {
                float rv = R_sm[(hc8 + hh) * NN + j];
                u64 rv2 = pack2(rv, rv);
                ulonglong2 cc = *(const ulonglong2*)(C_sm + (hc8 + hh) * NN + k0);
                acc[hh][0] = add2(rv2, cc.x);
                acc[hh][1] = add2(rv2, cc.y);
            }

            #pragma unroll 3
            for (int d = 0; d < ND; d++) {
                const float* xb = x_smT + d * NN;
                float xj = xb[j];
                u64 xj2 = pack2(xj, xj);
                ulonglong2 xk = *(const ulonglong2*)(xb + k0);
                u64 pp0 = mul2(xj2, xk.x);
                u64 pp1 = mul2(xj2, xk.y);
                const ulonglong2* A2p = (const ulonglong2*)(A2_sm + d * NH + hc8);
                #pragma unroll
                for (int h2 = 0; h2 < 4; h2++) {
                    ulonglong2 aa = A2p[h2];
                    acc[2*h2+0][0] = fma2(aa.x, pp0, acc[2*h2+0][0]);
                    acc[2*h2+0][1] = fma2(aa.x, pp1, acc[2*h2+0][1]);
                    acc[2*h2+1][0] = fma2(aa.y, pp0, acc[2*h2+1][0]);
                    acc[2*h2+1][1] = fma2(aa.y, pp1, acc[2*h2+1][1]);
                }
            }

            #pragma unroll
            for (int hh = 0; hh < 8; hh++) {
                float l0, h0, l1, h1;
                unpack2(acc[hh][0], l0, h0);
                unpack2(acc[hh][1], l1, h1);
                pool[hh] += fmaxf(l0, 0.f) + fmaxf(h0, 0.f)
                          + fmaxf(l1, 0.f) + fmaxf(h1, 0.f);
            }
        }

        #pragma unroll
        for (int hh = 0; hh < 8; hh++) {
            float v = pool[hh];
            #pragma unroll
            for (int off = 16; off; off >>= 1)
                v += __shfl_xor_sync(0xffffffffu, v, off);
            if (lane == 0) part_sm[warp][hc8 + hh] = v;
        }
    }
    __syncthreads();

    if (t < NH) {
        float su = 0.f;
        #pragma unroll
        for (int w = 0; w < 6; w++) su += part_sm[w][t];
        g_partial[(b * NN + i) * NH + t] = su;
    }

    // ---- fused finalize: last block reduces ----
    __threadfence();
    __syncthreads();
    if (t == 0) {
        unsigned int prev = atomicInc(&g_done, NBLOCKS - 1);  // wraps -> replay-safe
        is_last = (prev == NBLOCKS - 1);
    }
    __syncthreads();
    if (!is_last) return;
    __threadfence();

    __shared__ float fin[NB][NH];
    for (int idx = t; idx < NB * NH; idx += NTHREADS) {
        int bb = idx >> 5;
        int h  = idx & 31;
        float P = 0.f;
        #pragma unroll 8
        for (int ii = 0; ii < NN; ii++)
            P += g_partial[(bb * NN + ii) * NH + h];
        P *= (1.0f / 110592.0f);
        P = fmaxf(P, 0.f);
        fin[bb][h] = P * out_w[h];
    }
    __syncthreads();
    if (t < NB) {
        float su = 0.f;
        #pragma unroll
        for (int h = 0; h < NH; h++) su += fin[t][h];
        out[t] = su + out_b[0];
    }
}

extern "C" void kernel_launch(void* const* d_in, const int* in_sizes, int n_in,
                              void* d_out, int out_size)
{
    const int*   xcat    = (const int*)  d_in[0];
    const float* xfeat   = (const float*)d_in[1];
    const float* embed   = (const float*)d_in[2];
    const float* coefs   = (const float*)d_in[3];
    const float* eq_bias = (const float*)d_in[4];
    const float* out_w   = (const float*)d_in[5];
    const float* out_b   = (const float*)d_in[6];
    float* out = (float*)d_out;

    dim3 grid(NN, NB);   // (i, b)
    eq3_main<<<grid, NTHREADS>>>(xcat, xfeat, embed, coefs, eq_bias,
                                 out_w, out_b, out);
}

// round 15
// speedup vs baseline: 1.2257x; 1.2257x over previous
#include <cuda_runtime.h>

// Eq3NetMini: B=8, N=48, EMBED=32, IN_DIM=33, N_OPS=8, HID=32
// y[b,h,i,j,k] = sum_d A[h,d]*x_j,d*x_k,d + R[h,j] + C[h,k] + base[h]
// R14: back to best config (8h x 6k, occ 2 = R7's 82.4us) + deep unroll (11)
// on the d-loop so ptxas fills the ~58% idle issue slots with cross-iteration
// ILP (issue% pinned at 42% across R7/R8/R11 = latency-bound, not occupancy).

#define NB 8
#define NN 48
#define ND 33
#define NH 32
#define NTHREADS 192
#define NBLOCKS (NB * NN)

typedef unsigned long long u64;

__device__ __forceinline__ u64 pack2(float lo, float hi) {
    u64 r; asm("mov.b64 %0,{%1,%2};" : "=l"(r) : "f"(lo), "f"(hi)); return r;
}
__device__ __forceinline__ void unpack2(u64 v, float& lo, float& hi) {
    asm("mov.b64 {%0,%1},%2;" : "=f"(lo), "=f"(hi) : "l"(v));
}
__device__ __forceinline__ u64 fma2(u64 a, u64 b, u64 c) {
    u64 r; asm("fma.rn.f32x2 %0,%1,%2,%3;" : "=l"(r) : "l"(a), "l"(b), "l"(c)); return r;
}
__device__ __forceinline__ u64 mul2(u64 a, u64 b) {
    u64 r; asm("mul.rn.f32x2 %0,%1,%2;" : "=l"(r) : "l"(a), "l"(b)); return r;
}
__device__ __forceinline__ u64 add2(u64 a, u64 b) {
    u64 r; asm("add.rn.f32x2 %0,%1,%2;" : "=l"(r) : "l"(a), "l"(b)); return r;
}

__device__ float g_partial[NB * NN * NH];
__device__ unsigned int g_done = 0;         // self-resets via atomicInc wrap

__global__ __launch_bounds__(NTHREADS, 2) void eq3_main(
    const int*   __restrict__ xcat,
    const float* __restrict__ xfeat,
    const float* __restrict__ embed,
    const float* __restrict__ coefs,     // (33, 8, 32): [d*256 + s*32 + h]
    const float* __restrict__ eq_bias,
    const float* __restrict__ out_w,
    const float* __restrict__ out_b,
    float*       __restrict__ out)
{
    __shared__ __align__(16) float  x_smT[ND * NN];   // x[d][row]
    __shared__ float  s_sm[ND];
    __shared__ float  base_sm[NH];
    __shared__ __align__(16) float2 A2_sm[ND * NH];   // {a,a} dup for f32x2
    __shared__ __align__(16) float2 BD_sm[ND * NH];   // {B,D} interleaved
    __shared__ __align__(16) float  R_sm[NH * NN];    // [h*48+j] (base folded)
    __shared__ __align__(16) float  C_sm[NH * NN];    // [h*48+k]
    __shared__ float  part_sm[6][NH];
    __shared__ bool   is_last;

    const int t = threadIdx.x;
    const int b = blockIdx.y;
    const int i = blockIdx.x;

    // ---- load x transposed ----
    for (int e = t; e < NN * ND; e += NTHREADS) {
        int d   = e / NN;
        int row = e - d * NN;
        x_smT[e] = (d < 32) ? embed[xcat[b * NN + row] * 32 + d]
                            : xfeat[b * NN + row];
    }
    __syncthreads();

    // ---- column means ----
    if (t < ND) {
        const float* xr = x_smT + t * NN;
        float su = 0.f;
        #pragma unroll 8
        for (int r = 0; r < NN; r++) su += xr[r];
        s_sm[t] = su * (1.0f / 48.0f);
    }
    __syncthreads();

    // ---- per-block coefficient combos ----
    for (int e = t; e < ND * NH; e += NTHREADS) {
        int d = e >> 5;
        int h = e & 31;
        float xi = x_smT[d * NN + i];
        float s  = s_sm[d];
        const float* c = coefs + d * 256 + h;
        float a = c[0] * xi + c[32] * s;                        // op0+op1
        A2_sm[e] = make_float2(a, a);
        BD_sm[e] = make_float2((c[96] * xi + c[160] * s) * s,   // B -> R(j)
                               (c[64] * xi + c[128] * s) * s);  // D -> C(k)
    }
    if (t < NH) {
        float acc = eq_bias[t];
        for (int d = 0; d < ND; d++) {
            float xi = x_smT[d * NN + i];
            float s  = s_sm[d];
            const float* c = coefs + d * 256 + t;
            acc += (c[192] * xi + c[224] * s) * s * s;          // op6+op7
        }
        base_sm[t] = acc;
    }
    __syncthreads();

    // ---- R[h,j] (base folded) and C[h,k], vectorized {r,cc} ----
    for (int e = t; e < NH * NN; e += NTHREADS) {
        int h = e / NN;
        int j = e - h * NN;
        u64 rc = pack2(base_sm[h], 0.f);
        const u64* bd = (const u64*)(BD_sm + h);
        #pragma unroll 3
        for (int d = 0; d < ND; d++) {
            float xv = x_smT[d * NN + j];
            rc = fma2(bd[d * NH], pack2(xv, xv), rc);
        }
        float r, cc;
        unpack2(rc, r, cc);
        R_sm[e] = r;
        C_sm[e] = cc;
    }
    __syncthreads();

    // ---- main: per-thread (1 j) x (6 k) x (8 h), 2 tiles, 4 h-chunks ----
    const int lane = t & 31;
    const int warp = t >> 5;

    for (int hc = 0; hc < 4; hc++) {
        const int hc8 = hc * 8;
        float pool[8];
        #pragma unroll
        for (int hh = 0; hh < 8; hh++) pool[hh] = 0.f;

        #pragma unroll
        for (int tile = 0; tile < 2; tile++) {
            const int p  = t + NTHREADS * tile;   // 0..383
            const int j  = p >> 3;                // 0..47
            const int k0 = (p & 7) * 6;           // 0,6,...,42

            u64 acc[8][3];
            #pragma unroll
            for (int hh = 0; hh < 8; hh++) {
                float rv = R_sm[(hc8 + hh) * NN + j];
                u64 rv2 = pack2(rv, rv);
                const u64* cp = (const u64*)(C_sm + (hc8 + hh) * NN + k0);
                #pragma unroll
                for (int q = 0; q < 3; q++)
                    acc[hh][q] = add2(rv2, cp[q]);
            }

            const float* xj_p = x_smT + j;
            const u64*   xk_p = (const u64*)(x_smT + k0);
            const ulonglong2* A2p = (const ulonglong2*)(A2_sm + hc8);

            #pragma unroll 11
            for (int d = 0; d < ND; d++) {
                float xj = xj_p[d * NN];
                u64 xj2 = pack2(xj, xj);
                const u64* xk = (const u64*)((const float*)xk_p + d * NN);
                u64 pp0 = mul2(xj2, xk[0]);
                u64 pp1 = mul2(xj2, xk[1]);
                u64 pp2 = mul2(xj2, xk[2]);
                const ulonglong2* Ad = (const ulonglong2*)((const float2*)A2p + d * NH);
                #pragma unroll
                for (int h2 = 0; h2 < 4; h2++) {
                    ulonglong2 aa = Ad[h2];
                    acc[2*h2+0][0] = fma2(aa.x, pp0, acc[2*h2+0][0]);
                    acc[2*h2+0][1] = fma2(aa.x, pp1, acc[2*h2+0][1]);
                    acc[2*h2+0][2] = fma2(aa.x, pp2, acc[2*h2+0][2]);
                    acc[2*h2+1][0] = fma2(aa.y, pp0, acc[2*h2+1][0]);
                    acc[2*h2+1][1] = fma2(aa.y, pp1, acc[2*h2+1][1]);
                    acc[2*h2+1][2] = fma2(aa.y, pp2, acc[2*h2+1][2]);
                }
            }

            #pragma unroll
            for (int hh = 0; hh < 8; hh++) {
                float ss = 0.f;
                #pragma unroll
                for (int q = 0; q < 3; q++) {
                    float lo, hi;
                    unpack2(acc[hh][q], lo, hi);
                    ss += fmaxf(lo, 0.f) + fmaxf(hi, 0.f);
                }
                pool[hh] += ss;
            }
        }

        #pragma unroll
        for (int hh = 0; hh < 8; hh++) {
            float v = pool[hh];
            #pragma unroll
            for (int off = 16; off; off >>= 1)
                v += __shfl_xor_sync(0xffffffffu, v, off);
            if (lane == 0) part_sm[warp][hc8 + hh] = v;
        }
    }
    __syncthreads();

    if (t < NH) {
        float su = 0.f;
        #pragma unroll
        for (int w = 0; w < 6; w++) su += part_sm[w][t];
        g_partial[(b * NN + i) * NH + t] = su;
    }

    // ---- fused finalize: last block reduces ----
    __threadfence();
    __syncthreads();
    if (t == 0) {
        unsigned int prev = atomicInc(&g_done, NBLOCKS - 1);  // wraps -> replay-safe
        is_last = (prev == NBLOCKS - 1);
    }
    __syncthreads();
    if (!is_last) return;
    __threadfence();

    __shared__ float fin[NB][NH];
    for (int idx = t; idx < NB * NH; idx += NTHREADS) {
        int bb = idx >> 5;
        int h  = idx & 31;
        float P = 0.f;
        #pragma unroll 8
        for (int ii = 0; ii < NN; ii++)
            P += g_partial[(bb * NN + ii) * NH + h];
        P *= (1.0f / 110592.0f);
        P = fmaxf(P, 0.f);
        fin[bb][h] = P * out_w[h];
    }
    __syncthreads();
    if (t < NB) {
        float su = 0.f;
        #pragma unroll
        for (int h = 0; h < NH; h++) su += fin[t][h];
        out[t] = su + out_b[0];
    }
}

extern "C" void kernel_launch(void* const* d_in, const int* in_sizes, int n_in,
                              void* d_out, int out_size)
{
    const int*   xcat    = (const int*)  d_in[0];
    const float* xfeat   = (const float*)d_in[1];
    const float* embed   = (const float*)d_in[2];
    const float* coefs   = (const float*)d_in[3];
    const float* eq_bias = (const float*)d_in[4];
    const float* out_w   = (const float*)d_in[5];
    const float* out_b   = (const float*)d_in[6];
    float* out = (float*)d_out;

    dim3 grid(NN, NB);   // (i, b)
    eq3_main<<<grid, NTHREADS>>>(xcat, xfeat, embed, coefs, eq_bias,
                                 out_w, out_b, out);
}

// round 17
// speedup vs baseline: 1.5812x; 1.2901x over previous
#include <cuda_runtime.h>
#include <cstdint>

// Eq3NetMini via mma.sync (bf16 HMMA, plain sm_103 target — tcgen05 is not
// reachable: harness ptxas targets sm_103 without the 'a' suffix).
// Per (b,i) block: Y[p,h] = P[p,d] @ A_i[d,h], p=j*48+k (2304 rows in 18
// slabs of 128), K=33 padded to 48, N=32. bf16 2-term split, 3 passes
// (PhAh + PhAl + PlAh) accumulated in f32 -> rel err ~4e-6.
// Epilogue per slab: D + R[j,h] + C[k,h] (+base), relu, pool.

#define NB 8
#define NN 48
#define ND 33
#define NH 32
#define NTHREADS 128
#define NBLOCKS (NB * NN)
#define NSLAB 18

// dynamic shared layout (bytes)
#define P_HI   0          // 128 rows x 128B (48 bf16 + pad), chunk-skewed
#define P_LO   16384
#define XR_OFF 32768      // [48][34] f32
#define RT_OFF 39296      // [48][36] f32 (R + base, by j)
#define CT_OFF 46208      // [48][36] f32 (C, by k)
#define AF_OFF 53120      // [48][32] f32 (A coefs, d>=33 zero)
#define BD_OFF 59264      // [33][32] float2
#define S_OFF  67712      // 33 f32
#define BSE_OFF 67856     // 32 f32
#define PART_OFF 67984    // 4*32 f32
#define SMEM_BYTES 68608

typedef unsigned long long u64;
typedef unsigned int u32;

__device__ __forceinline__ u64 pack2(float lo, float hi) {
    u64 r; asm("mov.b64 %0,{%1,%2};" : "=l"(r) : "f"(lo), "f"(hi)); return r;
}
__device__ __forceinline__ void unpack2(u64 v, float& lo, float& hi) {
    asm("mov.b64 {%0,%1},%2;" : "=f"(lo), "=f"(hi) : "l"(v));
}
__device__ __forceinline__ u64 fma2(u64 a, u64 b, u64 c) {
    u64 r; asm("fma.rn.f32x2 %0,%1,%2,%3;" : "=l"(r) : "l"(a), "l"(b), "l"(c)); return r;
}
__device__ __forceinline__ u32 cvt_bf16x2(float hi, float lo) {
    u32 r; asm("cvt.rn.bf16x2.f32 %0,%1,%2;" : "=r"(r) : "f"(hi), "f"(lo)); return r;
}
__device__ __forceinline__ u32 smem_u32(const void* p) {
    u32 a; asm("{.reg .u64 t; cvta.to.shared.u64 t, %1; cvt.u32.u64 %0, t;}" : "=r"(a) : "l"(p));
    return a;
}
__device__ __forceinline__ void ldsm4(u32 r[4], u32 addr) {
    asm volatile("ldmatrix.sync.aligned.m8n8.x4.shared.b16 {%0,%1,%2,%3}, [%4];"
                 : "=r"(r[0]), "=r"(r[1]), "=r"(r[2]), "=r"(r[3]) : "r"(addr));
}
__device__ __forceinline__ void mma_bf16(float d[4], const u32 a[4], u32 b0, u32 b1) {
    asm("mma.sync.aligned.m16n8k16.row.col.f32.bf16.bf16.f32 "
        "{%0,%1,%2,%3}, {%4,%5,%6,%7}, {%8,%9}, {%0,%1,%2,%3};"
        : "+f"(d[0]), "+f"(d[1]), "+f"(d[2]), "+f"(d[3])
        : "r"(a[0]), "r"(a[1]), "r"(a[2]), "r"(a[3]), "r"(b0), "r"(b1));
}

__device__ float g_partial[NB * NN * NH];
__device__ unsigned int g_done = 0;

extern __shared__ __align__(1024) char smx[];

__global__ __launch_bounds__(NTHREADS) void eq3_main(
    const int*   __restrict__ xcat,
    const float* __restrict__ xfeat,
    const float* __restrict__ embed,
    const float* __restrict__ coefs,     // (33, 8, 32): [d*256 + s*32 + h]
    const float* __restrict__ eq_bias,
    const float* __restrict__ out_w,
    const float* __restrict__ out_b,
    float*       __restrict__ out)
{
    const int t = threadIdx.x;
    const int wid = t >> 5;
    const int lane = t & 31;
    const int b = blockIdx.y;
    const int i = blockIdx.x;

    float*  xR   = (float*) (smx + XR_OFF);   // [48][34]
    float*  RT   = (float*) (smx + RT_OFF);   // [48][36]
    float*  CT   = (float*) (smx + CT_OFF);   // [48][36]
    float*  AF   = (float*) (smx + AF_OFF);   // [48][32]
    float2* BD   = (float2*)(smx + BD_OFF);
    float*  Ssm  = (float*) (smx + S_OFF);
    float*  Bse  = (float*) (smx + BSE_OFF);
    float*  part = (float*) (smx + PART_OFF);
    const u32 sb = smem_u32(smx);

    // ---- zero P planes + AF (pad regions stay zero) ----
    for (int e = t; e < 32768 / 4; e += NTHREADS) ((u32*)smx)[e] = 0;
    for (int e = t; e < 48 * 32; e += NTHREADS) AF[e] = 0.f;

    // ---- load x row-major [row][d], col 33 = 0 pad ----
    for (int e = t; e < NN * 34; e += NTHREADS) {
        int row = e / 34, d = e - row * 34;
        float v = 0.f;
        if (d < 32)       v = embed[xcat[b * NN + row] * 32 + d];
        else if (d == 32) v = xfeat[b * NN + row];
        xR[e] = v;
    }
    __syncthreads();

    // ---- column means ----
    if (t < ND) {
        float su = 0.f;
        #pragma unroll 8
        for (int r = 0; r < NN; r++) su += xR[r * 34 + t];
        Ssm[t] = su * (1.0f / 48.0f);
    }
    __syncthreads();

    // ---- coef combos: AF (f32), BD, base ----
    for (int e = t; e < ND * NH; e += NTHREADS) {
        int d = e >> 5, h = e & 31;
        float xi = xR[i * 34 + d];
        float s  = Ssm[d];
        const float* c = coefs + d * 256 + h;
        AF[d * 32 + h] = c[0] * xi + c[32] * s;                 // op0+op1
        BD[d * NH + h] = make_float2((c[96] * xi + c[160] * s) * s,   // -> R(j)
                                     (c[64] * xi + c[128] * s) * s);  // -> C(k)
    }
    if (t < NH) {
        float acc = eq_bias[t];
        for (int d = 0; d < ND; d++) {
            float xi = xR[i * 34 + d];
            float s  = Ssm[d];
            const float* c = coefs + d * 256 + t;
            acc += (c[192] * xi + c[224] * s) * s * s;          // op6+op7
        }
        Bse[t] = acc;
    }
    __syncthreads();

    // ---- RT[j][h] = base + sum_d B*x ; CT[k][h] = sum_d D*x ----
    for (int e = t; e < NN * NH; e += NTHREADS) {
        int j = e >> 5, h = e & 31;
        u64 rc = pack2(Bse[h], 0.f);
        const u64* bd = (const u64*)(BD + h);
        const float* xj = xR + j * 34;
        #pragma unroll 3
        for (int d = 0; d < ND; d++)
            rc = fma2(bd[d * NH], pack2(xj[d], xj[d]), rc);
        float r, cc; unpack2(rc, r, cc);
        RT[j * 36 + h] = r;
        CT[j * 36 + h] = cc;
    }
    __syncthreads();

    // ---- precompute B-fragments (A_i coefs) into registers: hi/lo split ----
    // mma row.col B frag: b0={A[d0][h],A[d0+1][h]}, b1={A[d0+8][h],A[d0+9][h]}
    // d0 = kc*16+(lane%4)*2, h = nt*8+lane/4
    u32 BH[3][4][2], BL[3][4][2];
    {
        const int h  = (lane >> 2);
        const int dq = (lane & 3) * 2;
        #pragma unroll
        for (int kc = 0; kc < 3; kc++) {
            #pragma unroll
            for (int nt = 0; nt < 4; nt++) {
                int hh = nt * 8 + h;
                int d0 = kc * 16 + dq;
                float a00 = AF[d0 * 32 + hh],       a01 = AF[(d0 + 1) * 32 + hh];
                float a08 = AF[(d0 + 8) * 32 + hh], a09 = AF[(d0 + 9) * 32 + hh];
                u32 h0 = cvt_bf16x2(a01, a00);
                u32 h1 = cvt_bf16x2(a09, a08);
                float r00 = a00 - __uint_as_float(h0 << 16);
                float r01 = a01 - __uint_as_float(h0 & 0xffff0000u);
                float r08 = a08 - __uint_as_float(h1 << 16);
                float r09 = a09 - __uint_as_float(h1 & 0xffff0000u);
                BH[kc][nt][0] = h0;  BH[kc][nt][1] = h1;
                BL[kc][nt][0] = cvt_bf16x2(r01, r00);
                BL[kc][nt][1] = cvt_bf16x2(r09, r08);
            }
        }
    }

    float pool[4][2];
    #pragma unroll
    for (int nt = 0; nt < 4; nt++) { pool[nt][0] = 0.f; pool[nt][1] = 0.f; }

    // ---- slab loop ----
    for (int s = 0; s < NSLAB; s++) {
        // build P row t (hi + residual planes), chunk-skewed 16B layout
        {
            const int p = s * 128 + t;
            const int j = p / 48;
            const int k = p - j * 48;
            const float* xj = xR + j * 34;
            const float* xk = xR + k * 34;
            #pragma unroll
            for (int c = 0; c < 5; c++) {
                u32 whi[4], wlo[4];
                #pragma unroll
                for (int q = 0; q < 4; q++) {
                    int dp = c * 4 + q;
                    if (dp < 17) {
                        float2 a = *(const float2*)(xj + 2 * dp);
                        float2 d = *(const float2*)(xk + 2 * dp);
                        float f0 = a.x * d.x, f1 = a.y * d.y;
                        u32 hp = cvt_bf16x2(f1, f0);
                        float r0 = f0 - __uint_as_float(hp << 16);
                        float r1 = f1 - __uint_as_float(hp & 0xffff0000u);
                        whi[q] = hp;
                        wlo[q] = cvt_bf16x2(r1, r0);
                    } else { whi[q] = 0u; wlo[q] = 0u; }
                }
                u32 off = (u32)t * 128u + (u32)(((c + t) & 7) << 4);
                *(uint4*)(smx + P_HI + off) = make_uint4(whi[0], whi[1], whi[2], whi[3]);
                *(uint4*)(smx + P_LO + off) = make_uint4(wlo[0], wlo[1], wlo[2], wlo[3]);
            }
        }
        __syncthreads();

        // each warp: 2 m-tiles of 16 rows
        #pragma unroll
        for (int half = 0; half < 2; half++) {
            const int mb = (wid * 2 + half) * 16;
            const int rowL = mb + (lane & 15);
            const int csel = lane >> 4;

            u32 ph[3][4], pl[3][4];
            #pragma unroll
            for (int kc = 0; kc < 3; kc++) {
                int cl = 2 * kc + csel;
                u32 off = (u32)rowL * 128u + (u32)(((cl + rowL) & 7) << 4);
                ldsm4(ph[kc], sb + P_HI + off);
                ldsm4(pl[kc], sb + P_LO + off);
            }

            float dd[4][4];
            #pragma unroll
            for (int nt = 0; nt < 4; nt++)
                #pragma unroll
                for (int q = 0; q < 4; q++) dd[nt][q] = 0.f;

            #pragma unroll
            for (int kc = 0; kc < 3; kc++) {
                #pragma unroll
                for (int nt = 0; nt < 4; nt++) {
                    mma_bf16(dd[nt], ph[kc], BH[kc][nt][0], BH[kc][nt][1]);
                    mma_bf16(dd[nt], ph[kc], BL[kc][nt][0], BL[kc][nt][1]);
                    mma_bf16(dd[nt], pl[kc], BH[kc][nt][0], BH[kc][nt][1]);
                }
            }

            // epilogue: D + R[j] + C[k], relu, pool
            const int p0 = s * 128 + mb + (lane >> 2);
            const int p1 = p0 + 8;
            const int j0 = p0 / 48, k0 = p0 - j0 * 48;
            const int j1 = p1 / 48, k1 = p1 - j1 * 48;
            const float* rt0 = RT + j0 * 36;
            const float* ct0 = CT + k0 * 36;
            const float* rt1 = RT + j1 * 36;
            const float* ct1 = CT + k1 * 36;
            const int h0 = (lane & 3) * 2;
            #pragma unroll
            for (int nt = 0; nt < 4; nt++) {
                const int hb = nt * 8 + h0;
                float2 R0 = *(const float2*)(rt0 + hb);
                float2 C0 = *(const float2*)(ct0 + hb);
                float2 R1 = *(const float2*)(rt1 + hb);
                float2 C1 = *(const float2*)(ct1 + hb);
                pool[nt][0] += fmaxf(dd[nt][0] + R0.x + C0.x, 0.f)
                             + fmaxf(dd[nt][2] + R1.x + C1.x, 0.f);
                pool[nt][1] += fmaxf(dd[nt][1] + R0.y + C0.y, 0.f)
                             + fmaxf(dd[nt][3] + R1.y + C1.y, 0.f);
            }
        }
        __syncthreads();   // P planes reusable next slab
    }

    // ---- reduce pool: lanes sharing (lane%4) hold same h pair ----
    #pragma unroll
    for (int nt = 0; nt < 4; nt++) {
        #pragma unroll
        for (int c = 0; c < 2; c++) {
            float v = pool[nt][c];
            v += __shfl_xor_sync(0xffffffffu, v, 4);
            v += __shfl_xor_sync(0xffffffffu, v, 8);
            v += __shfl_xor_sync(0xffffffffu, v, 16);
            if (lane < 4) part[wid * 32 + nt * 8 + lane * 2 + c] = v;
        }
    }
    __syncthreads();
    if (t < NH) {
        float su = part[t] + part[32 + t] + part[64 + t] + part[96 + t];
        g_partial[(b * NN + i) * NH + t] = su;
    }

    // ---- fused finalize: last block reduces ----
    __shared__ bool is_last;
    __threadfence();
    __syncthreads();
    if (t == 0) {
        unsigned int prev = atomicInc(&g_done, NBLOCKS - 1);  // wraps -> replay-safe
        is_last = (prev == NBLOCKS - 1);
    }
    __syncthreads();
    if (!is_last) return;
    __threadfence();

    float* fin = (float*)(smx + XR_OFF);  // reuse scratch: [8][32]
    for (int idx = t; idx < NB * NH; idx += NTHREADS) {
        int bb = idx >> 5, h = idx & 31;
        float P = 0.f;
        #pragma unroll 8
        for (int ii = 0; ii < NN; ii++)
            P += g_partial[(bb * NN + ii) * NH + h];
        P *= (1.0f / 110592.0f);
        P = fmaxf(P, 0.f);
        fin[bb * NH + h] = P * out_w[h];
    }
    __syncthreads();
    if (t < NB) {
        float su = 0.f;
        #pragma unroll
        for (int h = 0; h < NH; h++) su += fin[t * NH + h];
        out[t] = su + out_b[0];
    }
}

extern "C" void kernel_launch(void* const* d_in, const int* in_sizes, int n_in,
                              void* d_out, int out_size)
{
    const int*   xcat    = (const int*)  d_in[0];
    const float* xfeat   = (const float*)d_in[1];
    const float* embed   = (const float*)d_in[2];
    const float* coefs   = (const float*)d_in[3];
    const float* eq_bias = (const float*)d_in[4];
    const float* out_w   = (const float*)d_in[5];
    const float* out_b   = (const float*)d_in[6];
    float* out = (float*)d_out;

    cudaFuncSetAttribute(eq3_main, cudaFuncAttributeMaxDynamicSharedMemorySize,
                         SMEM_BYTES);
    dim3 grid(NN, NB);   // (i, b)
    eq3_main<<<grid, NTHREADS, SMEM_BYTES>>>(xcat, xfeat, embed, coefs, eq_bias,
                                             out_w, out_b, out);
}